// round 13
// baseline (speedup 1.0000x reference)
#include <cuda_runtime.h>

#define NIMG 32
#define C    512
#define HW   1024
#define NK   8        // Taylor terms k = 0..7

// ---- scratch (device globals; no allocation allowed) ----
__device__ float d_gap[NIMG * C];
__device__ unsigned long long d_u2[NIMG * C * NK];   // (q^k, q^k) packed f32x2
__device__ unsigned long long d_v2[NIMG * C * NK];   // (q^k/(k! Z), same) packed

// ---- packed f32x2 helpers (only reachable via PTX on sm_103a) ----
__device__ __forceinline__ unsigned long long fma2(unsigned long long a,
                                                   unsigned long long b,
                                                   unsigned long long c) {
    unsigned long long d;
    asm("fma.rn.f32x2 %0, %1, %2, %3;" : "=l"(d) : "l"(a), "l"(b), "l"(c));
    return d;
}
__device__ __forceinline__ unsigned long long mul2(unsigned long long a,
                                                   unsigned long long b) {
    unsigned long long d;
    asm("mul.rn.f32x2 %0, %1, %2;" : "=l"(d) : "l"(a), "l"(b));
    return d;
}
__device__ __forceinline__ unsigned long long add2(unsigned long long a,
                                                   unsigned long long b) {
    unsigned long long d;
    asm("add.rn.f32x2 %0, %1, %2;" : "=l"(d) : "l"(a), "l"(b));
    return d;
}
__device__ __forceinline__ unsigned long long pack2(float x, float y) {
    unsigned long long d;
    asm("mov.b64 %0, {%1, %2};" : "=l"(d) : "f"(x), "f"(y));
    return d;
}

// ============================================================================
// Kernel 1: global average pool. One CTA per (n, c) plane of 1024 floats.
// Also streams all of x through L2 (64 MB fits in 126 MB L2) for kernel 3.
// ============================================================================
__global__ void gap_kernel(const float* __restrict__ x) {
    int plane = blockIdx.x;                       // n*C + c
    const float4* p = (const float4*)x + (size_t)plane * 256;
    float4 v = p[threadIdx.x];                    // 256 threads * 4 floats
    float s = v.x + v.y + v.z + v.w;
    #pragma unroll
    for (int o = 16; o; o >>= 1) s += __shfl_xor_sync(0xFFFFFFFFu, s, o);
    __shared__ float sm[8];
    if ((threadIdx.x & 31) == 0) sm[threadIdx.x >> 5] = s;
    __syncthreads();
    if (threadIdx.x == 0) {
        float t = 0.f;
        #pragma unroll
        for (int i = 0; i < 8; i++) t += sm[i];
        d_gap[plane] = t * (1.0f / HW);
    }
}

// ============================================================================
// Kernel 2: per image — conv5 over channel dim, sigmoid, moment sums S_k,
// softmax partition Z = sum_k S_k^2 / k!, emit duplicated coef tables.
// grid = NIMG, block = 512 (one thread per channel).
// ============================================================================
__global__ void coef_kernel(const float* __restrict__ wq,
                            const float* __restrict__ bq) {
    int n = blockIdx.x;
    int c = threadIdx.x;
    __shared__ float sg[C];
    __shared__ float red[NK][16];

    sg[c] = d_gap[n * C + c];
    __syncthreads();

    // cross-correlation, kernel 5, SAME zero padding
    float acc = bq[0];
    #pragma unroll
    for (int j = 0; j < 5; j++) {
        int idx = c + j - 2;
        float g = (idx >= 0 && idx < C) ? sg[idx] : 0.0f;
        acc += g * wq[j];
    }
    float q = 1.0f / (1.0f + expf(-acc));

    // S_k = sum_c q_c^k  (block reduce, 8 values)
    float pw = 1.0f;
    #pragma unroll
    for (int k = 0; k < NK; k++) {
        float v = pw;
        #pragma unroll
        for (int o = 16; o; o >>= 1) v += __shfl_xor_sync(0xFFFFFFFFu, v, o);
        if ((c & 31) == 0) red[k][c >> 5] = v;
        pw *= q;
    }
    __syncthreads();

    const float invfact[NK] = {1.f, 1.f, 0.5f, 1.f / 6.f, 1.f / 24.f,
                               1.f / 120.f, 1.f / 720.f, 1.f / 5040.f};
    float Z = 0.0f;
    #pragma unroll
    for (int k = 0; k < NK; k++) {
        float S = 0.0f;
        #pragma unroll
        for (int w = 0; w < 16; w++) S += red[k][w];
        Z += S * S * invfact[k];
    }
    float invZ = 1.0f / Z;

    pw = 1.0f;
    size_t base = ((size_t)n * C + c) * NK;
    #pragma unroll
    for (int k = 0; k < NK; k++) {
        float u = pw;
        float v = u * invfact[k] * invZ;
        d_u2[base + k] = pack2(u, u);
        d_v2[base + k] = pack2(v, v);
        pw *= q;
    }
}

// ============================================================================
// Kernel 3: the attention pass.
//   grid = NIMG*4 CTAs of 512 threads. CTA = (image n, pixel part of 256 px).
//   thread = (channel-eighth e of 64 ch) x (pixel quad qi of 4 px).
//   Loop 1: t_k[quad] += x[c, quad] * q_c^k     (packed f32x2, LDG.128)
//   SMEM 8-way reduce over channel-eighths.
//   Loop 2: out[d, quad] = x[d, quad] * sum_k v_k[d] * t_k[quad]
// SMEM: u2 table 32KB + v2 table 32KB + scratch 64KB = 128KB dynamic.
// ============================================================================
__global__ void __launch_bounds__(512, 1)
att_kernel(const float* __restrict__ x, float* __restrict__ out) {
    extern __shared__ unsigned long long smem[];
    unsigned long long* su = smem;                 // C*NK ull  = 32 KB
    unsigned long long* sv = smem + C * NK;        // C*NK ull  = 32 KB
    ulonglong2* scr = (ulonglong2*)(smem + 2 * C * NK);  // NK*8*64 u2 = 64 KB

    const int n    = blockIdx.x >> 2;
    const int part = blockIdx.x & 3;
    const int tid  = threadIdx.x;
    const int e    = tid >> 6;    // channel eighth 0..7
    const int qi   = tid & 63;    // quad index within CTA

    // load coefficient tables (2048 float4 each)
    {
        const float4* gu = (const float4*)(d_u2 + (size_t)n * C * NK);
        const float4* gv = (const float4*)(d_v2 + (size_t)n * C * NK);
        float4* s4u = (float4*)su;
        float4* s4v = (float4*)sv;
        #pragma unroll
        for (int i = 0; i < 4; i++) {
            int idx = tid + i * 512;
            s4u[idx] = gu[idx];
            s4v[idx] = gv[idx];
        }
    }
    __syncthreads();

    const int quad  = part * 64 + qi;              // 0..255 within image
    const int cbase = e * 64;
    const ulonglong2* X = (const ulonglong2*)x + (size_t)n * C * 256;
    ulonglong2*       O = (ulonglong2*)out + (size_t)n * C * 256;

    // ---- loop 1: packed moments t_k over this thread's 64 channels ----
    unsigned long long t01[NK], t23[NK];
    #pragma unroll
    for (int k = 0; k < NK; k++) { t01[k] = 0ull; t23[k] = 0ull; }

    #pragma unroll 4
    for (int c = 0; c < 64; c++) {
        int ch = cbase + c;
        ulonglong2 xv = X[(size_t)ch * 256 + quad];        // 4 pixels
        const ulonglong2* row = (const ulonglong2*)(su + (size_t)ch * NK);
        ulonglong2 wa = row[0], wb = row[1], wc = row[2], wd = row[3];
        unsigned long long w[NK] = {wa.x, wa.y, wb.x, wb.y, wc.x, wc.y, wd.x, wd.y};
        #pragma unroll
        for (int k = 0; k < NK; k++) {
            t01[k] = fma2(xv.x, w[k], t01[k]);
            t23[k] = fma2(xv.y, w[k], t23[k]);
        }
    }

    // ---- reduce over the 8 channel-eighths via SMEM ([k][e][qi]: conflict-free) ----
    #pragma unroll
    for (int k = 0; k < NK; k++)
        scr[(k * 8 + e) * 64 + qi] = make_ulonglong2(t01[k], t23[k]);
    __syncthreads();
    #pragma unroll
    for (int k = 0; k < NK; k++) {
        unsigned long long a01 = 0ull, a23 = 0ull;
        #pragma unroll
        for (int ee = 0; ee < 8; ee++) {
            ulonglong2 v = scr[(k * 8 + ee) * 64 + qi];
            a01 = add2(a01, v.x);
            a23 = add2(a23, v.y);
        }
        t01[k] = a01;
        t23[k] = a23;
    }

    // ---- loop 2: out[d, quad] = x[d, quad] * dot(v[d], t) ----
    #pragma unroll 4
    for (int c = 0; c < 64; c++) {
        int ch = cbase + c;
        const ulonglong2* row = (const ulonglong2*)(sv + (size_t)ch * NK);
        ulonglong2 wa = row[0], wb = row[1], wc = row[2], wd = row[3];
        unsigned long long w[NK] = {wa.x, wa.y, wb.x, wb.y, wc.x, wc.y, wd.x, wd.y};
        unsigned long long r01 = mul2(w[0], t01[0]);
        unsigned long long r23 = mul2(w[0], t23[0]);
        #pragma unroll
        for (int k = 1; k < NK; k++) {
            r01 = fma2(w[k], t01[k], r01);
            r23 = fma2(w[k], t23[k], r23);
        }
        ulonglong2 xv = X[(size_t)ch * 256 + quad];
        ulonglong2 ov;
        ov.x = mul2(xv.x, r01);
        ov.y = mul2(xv.y, r23);
        O[(size_t)ch * 256 + quad] = ov;
    }
}

// ============================================================================
extern "C" void kernel_launch(void* const* d_in, const int* in_sizes, int n_in,
                              void* d_out, int out_size) {
    const float* x  = (const float*)d_in[0];   // (32, 512, 32, 32) f32
    const float* wq = (const float*)d_in[1];   // (1, 1, 5) f32
    const float* bq = (const float*)d_in[2];   // (1,) f32
    float* out = (float*)d_out;

    cudaFuncSetAttribute(att_kernel,
                         cudaFuncAttributeMaxDynamicSharedMemorySize, 128 * 1024);

    gap_kernel<<<NIMG * C, 256>>>(x);
    coef_kernel<<<NIMG, 512>>>(wq, bq);
    att_kernel<<<NIMG * 4, 512, 128 * 1024>>>(x, out);
}

// round 14
// speedup vs baseline: 1.0143x; 1.0143x over previous
#include <cuda_runtime.h>

#define NIMG 32
#define C    512
#define HW   1024
#define NK   8        // Taylor terms k = 0..7

// ---- scratch (device globals; no allocation allowed) ----
__device__ float d_gap[NIMG * C];
__device__ unsigned long long d_u2[NIMG * C * NK];   // (q^k, q^k) packed f32x2
__device__ unsigned long long d_v2[NIMG * C * NK];   // (q^k/(k! Z), same) packed

// ---- packed f32x2 helpers (only reachable via PTX on sm_103a) ----
__device__ __forceinline__ unsigned long long fma2(unsigned long long a,
                                                   unsigned long long b,
                                                   unsigned long long c) {
    unsigned long long d;
    asm("fma.rn.f32x2 %0, %1, %2, %3;" : "=l"(d) : "l"(a), "l"(b), "l"(c));
    return d;
}
__device__ __forceinline__ unsigned long long mul2(unsigned long long a,
                                                   unsigned long long b) {
    unsigned long long d;
    asm("mul.rn.f32x2 %0, %1, %2;" : "=l"(d) : "l"(a), "l"(b));
    return d;
}
__device__ __forceinline__ unsigned long long add2(unsigned long long a,
                                                   unsigned long long b) {
    unsigned long long d;
    asm("add.rn.f32x2 %0, %1, %2;" : "=l"(d) : "l"(a), "l"(b));
    return d;
}
__device__ __forceinline__ unsigned long long pack2(float x, float y) {
    unsigned long long d;
    asm("mov.b64 %0, {%1, %2};" : "=l"(d) : "f"(x), "f"(y));
    return d;
}

// ============================================================================
// Kernel 1: global average pool. One CTA per (n, c) plane of 1024 floats.
// Also streams all of x through L2 (64 MB fits in 126 MB L2) for kernel 3.
// ============================================================================
__global__ void gap_kernel(const float* __restrict__ x) {
    int plane = blockIdx.x;                       // n*C + c
    const float4* p = (const float4*)x + (size_t)plane * 256;
    float4 v = p[threadIdx.x];                    // 256 threads * 4 floats
    float s = v.x + v.y + v.z + v.w;
    #pragma unroll
    for (int o = 16; o; o >>= 1) s += __shfl_xor_sync(0xFFFFFFFFu, s, o);
    __shared__ float sm[8];
    if ((threadIdx.x & 31) == 0) sm[threadIdx.x >> 5] = s;
    __syncthreads();
    if (threadIdx.x == 0) {
        float t = 0.f;
        #pragma unroll
        for (int i = 0; i < 8; i++) t += sm[i];
        d_gap[plane] = t * (1.0f / HW);
    }
}

// ============================================================================
// Kernel 2: per image — conv5 over channel dim, sigmoid, moment sums S_k,
// softmax partition Z = sum_k S_k^2 / k!, emit duplicated coef tables.
// grid = NIMG, block = 512 (one thread per channel).
// ============================================================================
__global__ void coef_kernel(const float* __restrict__ wq,
                            const float* __restrict__ bq) {
    int n = blockIdx.x;
    int c = threadIdx.x;
    __shared__ float sg[C];
    __shared__ float red[NK][16];

    sg[c] = d_gap[n * C + c];
    __syncthreads();

    // cross-correlation, kernel 5, SAME zero padding
    float acc = bq[0];
    #pragma unroll
    for (int j = 0; j < 5; j++) {
        int idx = c + j - 2;
        float g = (idx >= 0 && idx < C) ? sg[idx] : 0.0f;
        acc += g * wq[j];
    }
    float q = 1.0f / (1.0f + expf(-acc));

    // S_k = sum_c q_c^k  (block reduce, 8 values)
    float pw = 1.0f;
    #pragma unroll
    for (int k = 0; k < NK; k++) {
        float v = pw;
        #pragma unroll
        for (int o = 16; o; o >>= 1) v += __shfl_xor_sync(0xFFFFFFFFu, v, o);
        if ((c & 31) == 0) red[k][c >> 5] = v;
        pw *= q;
    }
    __syncthreads();

    const float invfact[NK] = {1.f, 1.f, 0.5f, 1.f / 6.f, 1.f / 24.f,
                               1.f / 120.f, 1.f / 720.f, 1.f / 5040.f};
    float Z = 0.0f;
    #pragma unroll
    for (int k = 0; k < NK; k++) {
        float S = 0.0f;
        #pragma unroll
        for (int w = 0; w < 16; w++) S += red[k][w];
        Z += S * S * invfact[k];
    }
    float invZ = 1.0f / Z;

    pw = 1.0f;
    size_t base = ((size_t)n * C + c) * NK;
    #pragma unroll
    for (int k = 0; k < NK; k++) {
        float u = pw;
        float v = u * invfact[k] * invZ;
        d_u2[base + k] = pack2(u, u);
        d_v2[base + k] = pack2(v, v);
        pw *= q;
    }
}

// ============================================================================
// Kernel 3: the attention pass.
//   grid = NIMG*4 CTAs of 512 threads. CTA = (image n, pixel part of 256 px).
//   thread = (channel-eighth e of 64 ch) x (pixel quad qi of 4 px).
//   Loop 1: t_k[quad] += x[c, quad] * q_c^k     (packed f32x2, LDG.128)
//   SMEM 8-way reduce over channel-eighths.
//   Loop 2: out[d, quad] = x[d, quad] * sum_k v_k[d] * t_k[quad]
// SMEM: u2 table 32KB + v2 table 32KB + scratch 64KB = 128KB dynamic.
// ============================================================================
__global__ void __launch_bounds__(512, 1)
att_kernel(const float* __restrict__ x, float* __restrict__ out) {
    extern __shared__ unsigned long long smem[];
    unsigned long long* su = smem;                 // C*NK ull  = 32 KB
    unsigned long long* sv = smem + C * NK;        // C*NK ull  = 32 KB
    ulonglong2* scr = (ulonglong2*)(smem + 2 * C * NK);  // NK*8*64 u2 = 64 KB

    const int n    = blockIdx.x >> 2;
    const int part = blockIdx.x & 3;
    const int tid  = threadIdx.x;
    const int e    = tid >> 6;    // channel eighth 0..7
    const int qi   = tid & 63;    // quad index within CTA

    // load coefficient tables (2048 float4 each)
    {
        const float4* gu = (const float4*)(d_u2 + (size_t)n * C * NK);
        const float4* gv = (const float4*)(d_v2 + (size_t)n * C * NK);
        float4* s4u = (float4*)su;
        float4* s4v = (float4*)sv;
        #pragma unroll
        for (int i = 0; i < 4; i++) {
            int idx = tid + i * 512;
            s4u[idx] = gu[idx];
            s4v[idx] = gv[idx];
        }
    }
    __syncthreads();

    const int quad  = part * 64 + qi;              // 0..255 within image
    const int cbase = e * 64;
    const ulonglong2* X = (const ulonglong2*)x + (size_t)n * C * 256;
    ulonglong2*       O = (ulonglong2*)out + (size_t)n * C * 256;

    // ---- loop 1: packed moments t_k over this thread's 64 channels ----
    unsigned long long t01[NK], t23[NK];
    #pragma unroll
    for (int k = 0; k < NK; k++) { t01[k] = 0ull; t23[k] = 0ull; }

    #pragma unroll 4
    for (int c = 0; c < 64; c++) {
        int ch = cbase + c;
        ulonglong2 xv = X[(size_t)ch * 256 + quad];        // 4 pixels
        const ulonglong2* row = (const ulonglong2*)(su + (size_t)ch * NK);
        ulonglong2 wa = row[0], wb = row[1], wc = row[2], wd = row[3];
        unsigned long long w[NK] = {wa.x, wa.y, wb.x, wb.y, wc.x, wc.y, wd.x, wd.y};
        #pragma unroll
        for (int k = 0; k < NK; k++) {
            t01[k] = fma2(xv.x, w[k], t01[k]);
            t23[k] = fma2(xv.y, w[k], t23[k]);
        }
    }

    // ---- reduce over the 8 channel-eighths via SMEM ([k][e][qi]: conflict-free) ----
    #pragma unroll
    for (int k = 0; k < NK; k++)
        scr[(k * 8 + e) * 64 + qi] = make_ulonglong2(t01[k], t23[k]);
    __syncthreads();
    #pragma unroll
    for (int k = 0; k < NK; k++) {
        unsigned long long a01 = 0ull, a23 = 0ull;
        #pragma unroll
        for (int ee = 0; ee < 8; ee++) {
            ulonglong2 v = scr[(k * 8 + ee) * 64 + qi];
            a01 = add2(a01, v.x);
            a23 = add2(a23, v.y);
        }
        t01[k] = a01;
        t23[k] = a23;
    }

    // ---- loop 2: out[d, quad] = x[d, quad] * dot(v[d], t) ----
    #pragma unroll 4
    for (int c = 0; c < 64; c++) {
        int ch = cbase + c;
        const ulonglong2* row = (const ulonglong2*)(sv + (size_t)ch * NK);
        ulonglong2 wa = row[0], wb = row[1], wc = row[2], wd = row[3];
        unsigned long long w[NK] = {wa.x, wa.y, wb.x, wb.y, wc.x, wc.y, wd.x, wd.y};
        unsigned long long r01 = mul2(w[0], t01[0]);
        unsigned long long r23 = mul2(w[0], t23[0]);
        #pragma unroll
        for (int k = 1; k < NK; k++) {
            r01 = fma2(w[k], t01[k], r01);
            r23 = fma2(w[k], t23[k], r23);
        }
        ulonglong2 xv = X[(size_t)ch * 256 + quad];
        ulonglong2 ov;
        ov.x = mul2(xv.x, r01);
        ov.y = mul2(xv.y, r23);
        O[(size_t)ch * 256 + quad] = ov;
    }
}

// ============================================================================
extern "C" void kernel_launch(void* const* d_in, const int* in_sizes, int n_in,
                              void* d_out, int out_size) {
    const float* x  = (const float*)d_in[0];   // (32, 512, 32, 32) f32
    const float* wq = (const float*)d_in[1];   // (1, 1, 5) f32
    const float* bq = (const float*)d_in[2];   // (1,) f32
    float* out = (float*)d_out;

    cudaFuncSetAttribute(att_kernel,
                         cudaFuncAttributeMaxDynamicSharedMemorySize, 128 * 1024);

    gap_kernel<<<NIMG * C, 256>>>(x);
    coef_kernel<<<NIMG, 512>>>(wq, bq);
    att_kernel<<<NIMG * 4, 512, 128 * 1024>>>(x, out);
}

// round 15
// speedup vs baseline: 1.0189x; 1.0046x over previous
#include <cuda_runtime.h>

#define NIMG 32
#define C    512
#define HW   1024
#define NK   8        // Taylor terms k = 0..7

// ---- scratch (device globals; no allocation allowed) ----
__device__ float d_gap[NIMG * C];
__device__ unsigned long long d_u2[NIMG * C * NK];   // (q^k, q^k) packed f32x2
__device__ unsigned long long d_v2[NIMG * C * NK];   // (q^k/(k! Z), same) packed

// ---- packed f32x2 helpers (only reachable via PTX on sm_103a) ----
__device__ __forceinline__ unsigned long long fma2(unsigned long long a,
                                                   unsigned long long b,
                                                   unsigned long long c) {
    unsigned long long d;
    asm("fma.rn.f32x2 %0, %1, %2, %3;" : "=l"(d) : "l"(a), "l"(b), "l"(c));
    return d;
}
__device__ __forceinline__ unsigned long long mul2(unsigned long long a,
                                                   unsigned long long b) {
    unsigned long long d;
    asm("mul.rn.f32x2 %0, %1, %2;" : "=l"(d) : "l"(a), "l"(b));
    return d;
}
__device__ __forceinline__ unsigned long long add2(unsigned long long a,
                                                   unsigned long long b) {
    unsigned long long d;
    asm("add.rn.f32x2 %0, %1, %2;" : "=l"(d) : "l"(a), "l"(b));
    return d;
}
__device__ __forceinline__ unsigned long long pack2(float x, float y) {
    unsigned long long d;
    asm("mov.b64 %0, {%1, %2};" : "=l"(d) : "f"(x), "f"(y));
    return d;
}

// ============================================================================
// Kernel 1: global average pool. One CTA per (n, c) plane of 1024 floats.
// Also streams all of x through L2 (64 MB fits in 126 MB L2) for kernel 3.
// ============================================================================
__global__ void gap_kernel(const float* __restrict__ x) {
    int plane = blockIdx.x;                       // n*C + c
    const float4* p = (const float4*)x + (size_t)plane * 256;
    float4 v = p[threadIdx.x];                    // 256 threads * 4 floats
    float s = v.x + v.y + v.z + v.w;
    #pragma unroll
    for (int o = 16; o; o >>= 1) s += __shfl_xor_sync(0xFFFFFFFFu, s, o);
    __shared__ float sm[8];
    if ((threadIdx.x & 31) == 0) sm[threadIdx.x >> 5] = s;
    __syncthreads();
    if (threadIdx.x == 0) {
        float t = 0.f;
        #pragma unroll
        for (int i = 0; i < 8; i++) t += sm[i];
        d_gap[plane] = t * (1.0f / HW);
    }
}

// ============================================================================
// Kernel 2: per image — conv5 over channel dim, sigmoid, moment sums S_k,
// softmax partition Z = sum_k S_k^2 / k!, emit duplicated coef tables.
// grid = NIMG, block = 512 (one thread per channel).
// ============================================================================
__global__ void coef_kernel(const float* __restrict__ wq,
                            const float* __restrict__ bq) {
    int n = blockIdx.x;
    int c = threadIdx.x;
    __shared__ float sg[C];
    __shared__ float red[NK][16];

    sg[c] = d_gap[n * C + c];
    __syncthreads();

    // cross-correlation, kernel 5, SAME zero padding
    float acc = bq[0];
    #pragma unroll
    for (int j = 0; j < 5; j++) {
        int idx = c + j - 2;
        float g = (idx >= 0 && idx < C) ? sg[idx] : 0.0f;
        acc += g * wq[j];
    }
    float q = 1.0f / (1.0f + expf(-acc));

    // S_k = sum_c q_c^k  (block reduce, 8 values)
    float pw = 1.0f;
    #pragma unroll
    for (int k = 0; k < NK; k++) {
        float v = pw;
        #pragma unroll
        for (int o = 16; o; o >>= 1) v += __shfl_xor_sync(0xFFFFFFFFu, v, o);
        if ((c & 31) == 0) red[k][c >> 5] = v;
        pw *= q;
    }
    __syncthreads();

    const float invfact[NK] = {1.f, 1.f, 0.5f, 1.f / 6.f, 1.f / 24.f,
                               1.f / 120.f, 1.f / 720.f, 1.f / 5040.f};
    float Z = 0.0f;
    #pragma unroll
    for (int k = 0; k < NK; k++) {
        float S = 0.0f;
        #pragma unroll
        for (int w = 0; w < 16; w++) S += red[k][w];
        Z += S * S * invfact[k];
    }
    float invZ = 1.0f / Z;

    pw = 1.0f;
    size_t base = ((size_t)n * C + c) * NK;
    #pragma unroll
    for (int k = 0; k < NK; k++) {
        float u = pw;
        float v = u * invfact[k] * invZ;
        d_u2[base + k] = pack2(u, u);
        d_v2[base + k] = pack2(v, v);
        pw *= q;
    }
}

// ============================================================================
// Kernel 3: the attention pass.
//   grid = NIMG*4 CTAs of 512 threads. CTA = (image n, pixel part of 256 px).
//   thread = (channel-eighth e of 64 ch) x (pixel quad qi of 4 px).
//   Loop 1: t_k[quad] += x[c, quad] * q_c^k     (packed f32x2, LDG.128)
//   SMEM 8-way reduce over channel-eighths.
//   Loop 2: out[d, quad] = x[d, quad] * sum_k v_k[d] * t_k[quad]
// SMEM: u2 table 32KB + v2 table 32KB + scratch 64KB = 128KB dynamic.
// ============================================================================
__global__ void __launch_bounds__(512, 1)
att_kernel(const float* __restrict__ x, float* __restrict__ out) {
    extern __shared__ unsigned long long smem[];
    unsigned long long* su = smem;                 // C*NK ull  = 32 KB
    unsigned long long* sv = smem + C * NK;        // C*NK ull  = 32 KB
    ulonglong2* scr = (ulonglong2*)(smem + 2 * C * NK);  // NK*8*64 u2 = 64 KB

    const int n    = blockIdx.x >> 2;
    const int part = blockIdx.x & 3;
    const int tid  = threadIdx.x;
    const int e    = tid >> 6;    // channel eighth 0..7
    const int qi   = tid & 63;    // quad index within CTA

    // load coefficient tables (2048 float4 each)
    {
        const float4* gu = (const float4*)(d_u2 + (size_t)n * C * NK);
        const float4* gv = (const float4*)(d_v2 + (size_t)n * C * NK);
        float4* s4u = (float4*)su;
        float4* s4v = (float4*)sv;
        #pragma unroll
        for (int i = 0; i < 4; i++) {
            int idx = tid + i * 512;
            s4u[idx] = gu[idx];
            s4v[idx] = gv[idx];
        }
    }
    __syncthreads();

    const int quad  = part * 64 + qi;              // 0..255 within image
    const int cbase = e * 64;
    const ulonglong2* X = (const ulonglong2*)x + (size_t)n * C * 256;
    ulonglong2*       O = (ulonglong2*)out + (size_t)n * C * 256;

    // ---- loop 1: packed moments t_k over this thread's 64 channels ----
    unsigned long long t01[NK], t23[NK];
    #pragma unroll
    for (int k = 0; k < NK; k++) { t01[k] = 0ull; t23[k] = 0ull; }

    #pragma unroll 4
    for (int c = 0; c < 64; c++) {
        int ch = cbase + c;
        ulonglong2 xv = X[(size_t)ch * 256 + quad];        // 4 pixels
        const ulonglong2* row = (const ulonglong2*)(su + (size_t)ch * NK);
        ulonglong2 wa = row[0], wb = row[1], wc = row[2], wd = row[3];
        unsigned long long w[NK] = {wa.x, wa.y, wb.x, wb.y, wc.x, wc.y, wd.x, wd.y};
        #pragma unroll
        for (int k = 0; k < NK; k++) {
            t01[k] = fma2(xv.x, w[k], t01[k]);
            t23[k] = fma2(xv.y, w[k], t23[k]);
        }
    }

    // ---- reduce over the 8 channel-eighths via SMEM ([k][e][qi]: conflict-free) ----
    #pragma unroll
    for (int k = 0; k < NK; k++)
        scr[(k * 8 + e) * 64 + qi] = make_ulonglong2(t01[k], t23[k]);
    __syncthreads();
    #pragma unroll
    for (int k = 0; k < NK; k++) {
        unsigned long long a01 = 0ull, a23 = 0ull;
        #pragma unroll
        for (int ee = 0; ee < 8; ee++) {
            ulonglong2 v = scr[(k * 8 + ee) * 64 + qi];
            a01 = add2(a01, v.x);
            a23 = add2(a23, v.y);
        }
        t01[k] = a01;
        t23[k] = a23;
    }

    // ---- loop 2: out[d, quad] = x[d, quad] * dot(v[d], t) ----
    #pragma unroll 4
    for (int c = 0; c < 64; c++) {
        int ch = cbase + c;
        const ulonglong2* row = (const ulonglong2*)(sv + (size_t)ch * NK);
        ulonglong2 wa = row[0], wb = row[1], wc = row[2], wd = row[3];
        unsigned long long w[NK] = {wa.x, wa.y, wb.x, wb.y, wc.x, wc.y, wd.x, wd.y};
        unsigned long long r01 = mul2(w[0], t01[0]);
        unsigned long long r23 = mul2(w[0], t23[0]);
        #pragma unroll
        for (int k = 1; k < NK; k++) {
            r01 = fma2(w[k], t01[k], r01);
            r23 = fma2(w[k], t23[k], r23);
        }
        ulonglong2 xv = X[(size_t)ch * 256 + quad];
        ulonglong2 ov;
        ov.x = mul2(xv.x, r01);
        ov.y = mul2(xv.y, r23);
        O[(size_t)ch * 256 + quad] = ov;
    }
}

// ============================================================================
extern "C" void kernel_launch(void* const* d_in, const int* in_sizes, int n_in,
                              void* d_out, int out_size) {
    const float* x  = (const float*)d_in[0];   // (32, 512, 32, 32) f32
    const float* wq = (const float*)d_in[1];   // (1, 1, 5) f32
    const float* bq = (const float*)d_in[2];   // (1,) f32
    float* out = (float*)d_out;

    cudaFuncSetAttribute(att_kernel,
                         cudaFuncAttributeMaxDynamicSharedMemorySize, 128 * 1024);

    gap_kernel<<<NIMG * C, 256>>>(x);
    coef_kernel<<<NIMG, 512>>>(wq, bq);
    att_kernel<<<NIMG * 4, 512, 128 * 1024>>>(x, out);
}